// round 10
// baseline (speedup 1.0000x reference)
#include <cuda_runtime.h>
#include <math.h>

#define H 256
#define W 256
#define NW 8                 // 256 bits per row
#define NPIX (4*H*W)         // 262144
#define NB 256               // 4 batches x 64 col-tiles (4 cols); 2 blocks/SM co-resident
#define NT 512

// ---------------- device state (reset by last block's epilogue) ----------------
__device__ unsigned g_maskb[8][H][NW];
__device__ unsigned g_rmax[8];
__device__ unsigned g_rmin[8] = {0x7f7fffffu,0x7f7fffffu,0x7f7fffffu,0x7f7fffffu,
                                 0x7f7fffffu,0x7f7fffffu,0x7f7fffffu,0x7f7fffffu};
__device__ double   g_sums[4];
__device__ unsigned g_bdone[4];      // per-batch: phase-P arrivals (target 64)
__device__ unsigned g_edone[4];      // per-batch: rmax/rmin arrivals (target 64)
__device__ unsigned g_count;

__global__ void __launch_bounds__(NT) k_fused(const float* __restrict__ ypred,
                                              const int*   __restrict__ ytrue,
                                              float*       __restrict__ out) {
    __shared__ __align__(16) struct {
        unsigned bits[2][H][NW];                              // 16KB masks
        union {
            struct { unsigned ss[2][2][H][2]; unsigned sd[2][2][H][2]; } sk; // 16KB
            float shg[2][4][257];                                            // 8.2KB
        } u;
        unsigned skelw[2][H];                                 // 2KB tile-word skeleton
    } S;
    __shared__ float s_red[4][16];
    __shared__ float s_rr[4];

    const int t = threadIdx.x;
    const int bat  = blockIdx.x >> 6;            // 64 blocks per batch
    const int tile = blockIdx.x & 63;
    const int c0   = tile * 4;
    const int wc0  = c0 >> 5;
    const int imgL = bat * 2, imgP = bat * 2 + 1;

    // ================= Phase P: ballots + bit packing (2 px/thread) =========
    {
        int base = blockIdx.x * 1024 + t * 2;
        float2 x2 = *(const float2*)&ypred[base];
        int2   y2 = *(const int2*)&ytrue[base];
        unsigned nibP = (x2.x > 0.f) | ((x2.y > 0.f) << 1);
        unsigned nibT = (y2.x > 0) | ((y2.y > 0) << 1);
        int lane = t & 31;
        unsigned sh = (lane & 15) * 2;
        unsigned wP = nibP << sh, wT = nibT << sh;
        #pragma unroll
        for (int o = 1; o < 16; o <<= 1) {
            wP |= __shfl_xor_sync(0xffffffffu, wP, o);
            wT |= __shfl_xor_sync(0xffffffffu, wT, o);
        }
        if ((lane & 15) == 0) {
            int row = (base >> 8) & 255, word = (base & 255) >> 5;
            g_maskb[imgL][row][word] = wT;
            g_maskb[imgP][row][word] = wP;
        }
    }
    // ---- per-batch barrier 1 (this batch's 64 blocks produced all masks) ----
    __syncthreads();
    if (t == 0) {
        __threadfence();
        atomicAdd(&g_bdone[bat], 1u);
        volatile unsigned* vb = &g_bdone[bat];
        while (*vb < 64u) __nanosleep(32);
        __threadfence();
    }
    __syncthreads();

    {   // load both bitboards (vectorized; imgP contiguous after imgL)
        uint4* dst = (uint4*)&S.bits[0][0][0];
        const uint4* src = (const uint4*)&g_maskb[imgL][0][0];
        #pragma unroll
        for (int j = 0; j < 2; j++) dst[t + j * NT] = src[t + j * NT];
    }
    __syncthreads();

    // ---- band skeleton: img split across thread halves; 1 sync/iter ------
    {
        int wbs = (c0 - 12) < 0 ? 0 : ((c0 - 12) >> 5);
        const int wb = wbs > 6 ? 6 : wbs;
        const int tw = wc0 - wb;
        const int im = t >> 8;            // 0: true, 1: pred
        const int r  = t & 255;
        const int ru = r > 0 ? r - 1 : 0;
        const int rd = r < H - 1 ? r + 1 : H - 1;

        unsigned cur0 = S.bits[im][r][wb], cur1 = S.bits[im][r][wb + 1];
        unsigned sk0 = 0u, sk1 = 0u;
        S.u.sk.ss[0][im][r][0] = cur0;
        S.u.sk.ss[0][im][r][1] = cur1;
        __syncthreads();

        int b = 0;
        for (int it = 0; it < 11; it++) {
            unsigned vu0 = (r == 0)     ? 0xffffffffu : S.u.sk.ss[b][im][ru][0];
            unsigned vu1 = (r == 0)     ? 0xffffffffu : S.u.sk.ss[b][im][ru][1];
            unsigned vd0 = (r == H - 1) ? 0xffffffffu : S.u.sk.ss[b][im][rd][0];
            unsigned vd1 = (r == H - 1) ? 0xffffffffu : S.u.sk.ss[b][im][rd][1];
            unsigned sl0 = (cur0 << 1) | 1u;
            unsigned sl1 = (cur1 << 1) | (cur0 >> 31);
            unsigned sr0 = (cur0 >> 1) | (cur1 << 31);
            unsigned sr1 = (cur1 >> 1) | 0x80000000u;
            unsigned e0 = vu0 & vd0 & cur0 & sl0 & sr0;
            unsigned e1 = vu1 & vd1 & cur1 & sl1 & sr1;
            unsigned h0 = e0 | (e0 << 1) | (e0 >> 1) | (e1 << 31);
            unsigned h1 = e1 | (e1 << 1) | (e0 >> 31) | (e1 >> 1);
            S.u.sk.ss[b ^ 1][im][r][0] = e0;
            S.u.sk.ss[b ^ 1][im][r][1] = e1;
            S.u.sk.sd[b ^ 1][im][r][0] = h0;
            S.u.sk.sd[b ^ 1][im][r][1] = h1;
            __syncthreads();
            unsigned o0 = h0, o1 = h1;
            if (r > 0)     { o0 |= S.u.sk.sd[b ^ 1][im][ru][0]; o1 |= S.u.sk.sd[b ^ 1][im][ru][1]; }
            if (r < H - 1) { o0 |= S.u.sk.sd[b ^ 1][im][rd][0]; o1 |= S.u.sk.sd[b ^ 1][im][rd][1]; }
            sk0 |= cur0 & ~o0;
            sk1 |= cur1 & ~o1;
            cur0 = e0; cur1 = e1;
            b ^= 1;
        }
        S.skelw[im][r] = tw ? sk1 : sk0;
        __syncthreads();                           // skeleton done; shg may overlay
    }

    // ---- horizontal EDT via bit scans: thread = (image, row), 4 cols -------
    {
        const int im = t >> 8;
        const int r  = t & 255;
        #pragma unroll 1
        for (int k = 0; k < 4; k++) {
            int c = c0 + k, kk = c & 31;
            int dl = 512, dr = 512;
            unsigned v = ~S.bits[im][r][wc0] & (0xffffffffu >> (31 - kk));
            int w = wc0;
            while (true) { if (v) { dl = c - (w * 32 + 31 - __clz(v)); break; }
                           if (--w < 0) break; v = ~S.bits[im][r][w]; }
            v = ~S.bits[im][r][wc0] & (0xffffffffu << kk);
            w = wc0;
            while (true) { if (v) { dr = (w * 32 + __ffs(v) - 1) - c; break; }
                           if (++w >= NW) break; v = ~S.bits[im][r][w]; }
            int g = min(min(dl, dr), 512);
            S.u.shg[im][k][r] = (float)(g * g);
        }
    }
    __syncthreads();

    // ---- vertical envelope: 2 rows/thread, both images, spec unroll-4 ------
    const int c4    = t & 3;
    const int ybase = (t >> 2) * 2;
    const int gc    = c0 + c4;
    const unsigned shbit = gc & 31;
    const float* cp0 = &S.u.shg[0][c4][0];
    const float* cp1 = &S.u.shg[1][c4][0];
    float dm0[2], dm1[2];
    #pragma unroll
    for (int k = 0; k < 2; k++) {
        int y = ybase + k;
        float m0 = cp0[y], m1 = cp1[y];
        int dy = 1;
        while ((float)(dy * dy) < fmaxf(m0, m1) && dy < H) {
            #pragma unroll
            for (int j = 0; j < 4; j++) {          // clamped = safe overestimates
                int d = dy + j;
                float d2 = (float)(d * d);
                int ya = y - d; ya = ya < 0 ? 0 : ya;
                int yb = y + d; yb = yb > H - 1 ? H - 1 : yb;
                m0 = fminf(m0, fminf(cp0[ya], cp0[yb]) + d2);
                m1 = fminf(m1, fminf(cp1[ya], cp1[yb]) + d2);
            }
            dy += 4;
        }
        unsigned mb0 = (S.bits[0][y][wc0] >> shbit) & 1u;
        unsigned mb1 = (S.bits[1][y][wc0] >> shbit) & 1u;
        dm0[k] = mb0 ? sqrtf(m0) : 0.0f;
        dm1[k] = mb1 ? sqrtf(m1) : 0.0f;
    }

    // ---- tile rmax/rmin for both images + per-batch barrier ----
    {
        float mxL = 0.f, mnL = __int_as_float(0x7f7fffff);
        float mxP = 0.f, mnP = __int_as_float(0x7f7fffff);
        #pragma unroll
        for (int k = 0; k < 2; k++) {
            int y = ybase + k;
            float srL = ((S.skelw[0][y] >> shbit) & 1u) ? dm0[k] : 0.f;
            float srP = ((S.skelw[1][y] >> shbit) & 1u) ? dm1[k] : 0.f;
            mxL = fmaxf(mxL, srL); mnL = fminf(mnL, srL);
            mxP = fmaxf(mxP, srP); mnP = fminf(mnP, srP);
        }
        #pragma unroll
        for (int o = 16; o; o >>= 1) {
            mxL = fmaxf(mxL, __shfl_xor_sync(0xffffffffu, mxL, o));
            mnL = fminf(mnL, __shfl_xor_sync(0xffffffffu, mnL, o));
            mxP = fmaxf(mxP, __shfl_xor_sync(0xffffffffu, mxP, o));
            mnP = fminf(mnP, __shfl_xor_sync(0xffffffffu, mnP, o));
        }
        if ((t & 31) == 0) {
            int w = t >> 5;
            s_red[0][w] = mxL; s_red[1][w] = mnL; s_red[2][w] = mxP; s_red[3][w] = mnP;
        }
        __syncthreads();
        if (t == 0) {
            float a = s_red[0][0], b = s_red[1][0], c = s_red[2][0], d = s_red[3][0];
            #pragma unroll
            for (int w = 1; w < 16; w++) {
                a = fmaxf(a, s_red[0][w]); b = fminf(b, s_red[1][w]);
                c = fmaxf(c, s_red[2][w]); d = fminf(d, s_red[3][w]);
            }
            atomicMax(&g_rmax[imgL], __float_as_uint(a));
            atomicMin(&g_rmin[imgL], __float_as_uint(b));
            atomicMax(&g_rmax[imgP], __float_as_uint(c));
            atomicMin(&g_rmin[imgP], __float_as_uint(d));
            __threadfence();
            atomicAdd(&g_edone[bat], 1u);
            volatile unsigned* eb = &g_edone[bat];
            while (*eb < 64u) __nanosleep(32);
            __threadfence();
            s_rr[0] = fmaxf(__uint_as_float(*(volatile unsigned*)&g_rmax[imgL]), 1.0f);
            s_rr[1] = fmaxf(__uint_as_float(*(volatile unsigned*)&g_rmin[imgL]), 1.0f);
            s_rr[2] = fmaxf(__uint_as_float(*(volatile unsigned*)&g_rmax[imgP]), 1.0f);
            s_rr[3] = fmaxf(__uint_as_float(*(volatile unsigned*)&g_rmin[imgP]), 1.0f);
        }
        __syncthreads();
    }
    const float rmaxL = s_rr[0], rminL = s_rr[1], rmaxP = s_rr[2], rminP = s_rr[3];
    const float irL = __fdividef(1.0f, rmaxL), irP = __fdividef(1.0f, rmaxP);

    // ---- q-maps + partial sums (pp recomputed from L2-hot ypred) ----
    float t1 = 0.f, d1 = 0.f, t2 = 0.f, d2s = 0.f;
    #pragma unroll
    for (int k = 0; k < 2; k++) {
        int y = ybase + k;
        bool mL = (S.bits[0][y][wc0] >> shbit) & 1u;
        bool mP = (S.bits[1][y][wc0] >> shbit) & 1u;
        bool sL = (S.skelw[0][y] >> shbit) & 1u;
        bool sP = (S.skelw[1][y] >> shbit) & 1u;
        float dl = dm0[k], dp = dm1[k];
        float x  = __ldg(&ypred[bat * 65536 + y * 256 + gc]);
        float p  = __fdividef(1.0f, 1.0f + __expf(-x));
        float pp = __fdividef(1.0f, 1.0f + __expf(1.0f - 2.0f * p));

        float q_vl   = mL ? fminf(dl, rmaxL) * irL : 0.f;
        float q_slvl = sL ? dl * irL : 0.f;
        float q_sl   = sL ? (rmaxL - dl + rminL) * irL : 0.f;
        float q_vp   = mP ? fminf(dp, rmaxP) * irP * pp : 0.f;
        float q_spvp = sP ? dp * irP * pp : 0.f;
        float q_sp   = sP ? (rmaxP - dp + rminP) * irP * pp : 0.f;
        t1  += q_sp * q_vl;
        d1  += (sP && !sL) ? q_spvp * q_sp : q_slvl * q_sp;   // combine_tensors
        t2  += q_sl * q_vp;
        d2s += (sL && !sP) ? q_slvl * q_sl : q_spvp * q_sl;
    }
    #pragma unroll
    for (int o = 16; o; o >>= 1) {
        t1  += __shfl_xor_sync(0xffffffffu, t1,  o);
        d1  += __shfl_xor_sync(0xffffffffu, d1,  o);
        t2  += __shfl_xor_sync(0xffffffffu, t2,  o);
        d2s += __shfl_xor_sync(0xffffffffu, d2s, o);
    }
    if ((t & 31) == 0) {
        int w = t >> 5;
        s_red[0][w] = t1; s_red[1][w] = d1; s_red[2][w] = t2; s_red[3][w] = d2s;
    }
    __syncthreads();
    if (t == 0) {
        double a0 = 0.0, a1 = 0.0, a2 = 0.0, a3 = 0.0;
        #pragma unroll
        for (int w = 0; w < 16; w++) {
            a0 += (double)s_red[0][w]; a1 += (double)s_red[1][w];
            a2 += (double)s_red[2][w]; a3 += (double)s_red[3][w];
        }
        atomicAdd(&g_sums[0], a0);
        atomicAdd(&g_sums[1], a1);
        atomicAdd(&g_sums[2], a2);
        atomicAdd(&g_sums[3], a3);
        __threadfence();
        unsigned done = atomicAdd(&g_count, 1u);
        if (done == NB - 1) {                      // last block: epilogue + reset
            double S1 = atomicAdd(&g_sums[0], 0.0);
            double D1 = atomicAdd(&g_sums[1], 0.0);
            double S2 = atomicAdd(&g_sums[2], 0.0);
            double D2 = atomicAdd(&g_sums[3], 0.0);
            double wp = (S1 + 1.0) / (D1 + 1.0);
            double ws = (S2 + 1.0) / (D2 + 1.0);
            out[0] = (float)(1.0 - 2.0 * (wp * ws) / (wp + ws));
            g_count = 0u;
            #pragma unroll
            for (int i = 0; i < 4; i++) { g_bdone[i] = 0u; g_edone[i] = 0u; g_sums[i] = 0.0; }
            #pragma unroll
            for (int i = 0; i < 8; i++) { g_rmax[i] = 0u; g_rmin[i] = 0x7f7fffffu; }
            __threadfence();
        }
    }
}

// ---------------- launch ----------------
extern "C" void kernel_launch(void* const* d_in, const int* in_sizes, int n_in,
                              void* d_out, int out_size) {
    const float* ypred = (const float*)d_in[0];
    const int*   ytrue = (const int*)d_in[1];
    float*       out   = (float*)d_out;
    k_fused<<<NB, NT>>>(ypred, ytrue, out);
}

// round 11
// speedup vs baseline: 1.1015x; 1.1015x over previous
#include <cuda_runtime.h>
#include <math.h>

#define H 256
#define W 256
#define NW 8                 // 256 bits per row
#define NPIX (4*H*W)         // 262144
#define NB 128               // 4 batches x 32 col-tiles (8 cols)
#define NT 512

// ---------------- device state (reset by last block's epilogue) ----------------
__device__ unsigned g_maskb[8][H][NW];
__device__ unsigned g_rmax[8];
__device__ unsigned g_rmin[8] = {0x7f7fffffu,0x7f7fffffu,0x7f7fffffu,0x7f7fffffu,
                                 0x7f7fffffu,0x7f7fffffu,0x7f7fffffu,0x7f7fffffu};
__device__ double   g_sums[4];
__device__ unsigned g_bdone[4];      // per-batch: phase-P arrivals (target 32)
__device__ unsigned g_edone[4];      // per-batch: rmax/rmin arrivals (target 32)
__device__ unsigned g_count;

__global__ void __launch_bounds__(NT) k_fused(const float* __restrict__ ypred,
                                              const int*   __restrict__ ytrue,
                                              float*       __restrict__ out) {
    __shared__ __align__(16) struct {
        unsigned bits[2][H][NW];      // 16KB   both images' masks
        unsigned ss[2][2][H];         // 8KB    1-word band, double-buffered
        float    shg[2][8][257];      // 16.4KB horizontal g^2 per image
        unsigned skelw[2][H];         // 2KB    band-coord skeleton word
    } S;
    __shared__ float s_red[4][16];
    __shared__ float s_rr[4];

    const int t = threadIdx.x;
    const int bat  = blockIdx.x >> 5;
    const int tile = blockIdx.x & 31;
    const int c0   = tile * 8;
    const int wc0  = c0 >> 5;
    const int imgL = bat * 2, imgP = bat * 2 + 1;
    // band window start: clamp(c0-12, 0, 224); clamped edges coincide with image edges
    int shB_ = c0 - 12; if (shB_ < 0) shB_ = 0; if (shB_ > 224) shB_ = 224;
    const int shB = shB_;

    // ================= Phase P: ballots + bit packing (4 px/thread) =========
    {
        int base = blockIdx.x * 2048 + t * 4;
        float4 x4 = *(const float4*)&ypred[base];
        int4   y4 = *(const int4*)&ytrue[base];
        unsigned nibP = (x4.x > 0.f) | ((x4.y > 0.f) << 1) | ((x4.z > 0.f) << 2) | ((x4.w > 0.f) << 3);
        unsigned nibT = (y4.x > 0) | ((y4.y > 0) << 1) | ((y4.z > 0) << 2) | ((y4.w > 0) << 3);
        int lane = t & 31;
        unsigned sh = (lane & 7) * 4;
        unsigned wP = nibP << sh, wT = nibT << sh;
        #pragma unroll
        for (int o = 1; o < 8; o <<= 1) {
            wP |= __shfl_xor_sync(0xffffffffu, wP, o);
            wT |= __shfl_xor_sync(0xffffffffu, wT, o);
        }
        if ((lane & 7) == 0) {
            int row = (base >> 8) & 255, word = (base & 255) >> 5;
            g_maskb[imgL][row][word] = wT;
            g_maskb[imgP][row][word] = wP;
        }
    }
    // ---- per-batch barrier 1 ----
    __syncthreads();
    if (t == 0) {
        __threadfence();
        atomicAdd(&g_bdone[bat], 1u);
        volatile unsigned* vb = &g_bdone[bat];
        while (*vb < 32u) __nanosleep(32);
        __threadfence();
    }
    __syncthreads();

    {   // load both bitboards (vectorized; imgP contiguous after imgL)
        uint4* dst = (uint4*)&S.bits[0][0][0];
        const uint4* src = (const uint4*)&g_maskb[imgL][0][0];
        #pragma unroll
        for (int j = 0; j < 2; j++) dst[t + j * NT] = src[t + j * NT];
    }
    __syncthreads();

    // ========== fused: 1-word band skeleton + hEDT (thread = (img, row)) ====
    {
        const int ws = shB >> 5, so = shB & 31;
        const int im = t >> 8;            // 0: true, 1: pred
        const int r  = t & 255;
        unsigned lo = S.bits[im][r][ws];
        unsigned hi = (ws < 7) ? S.bits[im][r][ws + 1] : 0u;
        unsigned cur = __funnelshift_r(lo, hi, so);
        unsigned skel = 0u;
        S.ss[0][im][r] = cur;
        __syncthreads();

        int b = 0;
        for (int it = 0; it < 11; it++) {
            // erode (cross SE); band-edge bits: image-edge semantics (1s) where clamped,
            // arbitrary-but-irrelevant (margin proof) in the interior.
            unsigned vu = (r == 0)     ? 0xffffffffu : S.ss[b][im][r - 1];
            unsigned vd = (r == H - 1) ? 0xffffffffu : S.ss[b][im][r + 1];
            unsigned e  = vu & vd & cur & ((cur << 1) | 1u) & ((cur >> 1) | 0x80000000u);
            S.ss[b ^ 1][im][r] = e;

            // hEDT column 'it' (independent work filling the barrier gap)
            if (it < 8) {
                int c = c0 + it, kk = c & 31;
                int dl = 512, dr = 512;
                unsigned v = ~S.bits[im][r][wc0] & (0xffffffffu >> (31 - kk));
                int w = wc0;
                while (true) { if (v) { dl = c - (w * 32 + 31 - __clz(v)); break; }
                               if (--w < 0) break; v = ~S.bits[im][r][w]; }
                v = ~S.bits[im][r][wc0] & (0xffffffffu << kk);
                w = wc0;
                while (true) { if (v) { dr = (w * 32 + __ffs(v) - 1) - c; break; }
                               if (++w >= NW) break; v = ~S.bits[im][r][w]; }
                int g = min(min(dl, dr), 512);
                S.shg[im][it][r] = (float)(g * g);
            }
            __syncthreads();

            // open = 3x3 dilation of e (separable; dilation distributes over OR)
            unsigned eu = (r == 0)     ? 0u : S.ss[b ^ 1][im][r - 1];
            unsigned ed = (r == H - 1) ? 0u : S.ss[b ^ 1][im][r + 1];
            unsigned vo = eu | e | ed;
            unsigned o  = vo | (vo << 1) | (vo >> 1);
            skel |= cur & ~o;
            cur = e;
            b ^= 1;
        }
        S.skelw[im][r] = skel;
        __syncthreads();
    }

    // ---- vertical envelope: 4 rows/thread, both images, spec unroll-4 ------
    const int c8    = t & 7;
    const int ybase = (t >> 3) * 4;
    const int gc    = c0 + c8;
    const unsigned shbit = gc & 31;        // bit within mask word wc0
    const unsigned skbit = gc - shB;       // bit within band skeleton word
    const float* cp0 = &S.shg[0][c8][0];
    const float* cp1 = &S.shg[1][c8][0];
    float dm0[4], dm1[4];
    #pragma unroll 1
    for (int k = 0; k < 4; k++) {
        int y = ybase + k;
        float m0 = cp0[y], m1 = cp1[y];
        int dy = 1;
        while ((float)(dy * dy) < fmaxf(m0, m1) && dy < H) {
            #pragma unroll
            for (int j = 0; j < 4; j++) {          // clamped = safe overestimates
                int d = dy + j;
                float d2 = (float)(d * d);
                int ya = y - d; ya = ya < 0 ? 0 : ya;
                int yb = y + d; yb = yb > H - 1 ? H - 1 : yb;
                m0 = fminf(m0, fminf(cp0[ya], cp0[yb]) + d2);
                m1 = fminf(m1, fminf(cp1[ya], cp1[yb]) + d2);
            }
            dy += 4;
        }
        unsigned mb0 = (S.bits[0][y][wc0] >> shbit) & 1u;
        unsigned mb1 = (S.bits[1][y][wc0] >> shbit) & 1u;
        dm0[k] = mb0 ? sqrtf(m0) : 0.0f;
        dm1[k] = mb1 ? sqrtf(m1) : 0.0f;
    }

    // ---- tile rmax/rmin for both images + per-batch barrier ----
    {
        float mxL = 0.f, mnL = __int_as_float(0x7f7fffff);
        float mxP = 0.f, mnP = __int_as_float(0x7f7fffff);
        #pragma unroll
        for (int k = 0; k < 4; k++) {
            int y = ybase + k;
            float srL = ((S.skelw[0][y] >> skbit) & 1u) ? dm0[k] : 0.f;
            float srP = ((S.skelw[1][y] >> skbit) & 1u) ? dm1[k] : 0.f;
            mxL = fmaxf(mxL, srL); mnL = fminf(mnL, srL);
            mxP = fmaxf(mxP, srP); mnP = fminf(mnP, srP);
        }
        #pragma unroll
        for (int o = 16; o; o >>= 1) {
            mxL = fmaxf(mxL, __shfl_xor_sync(0xffffffffu, mxL, o));
            mnL = fminf(mnL, __shfl_xor_sync(0xffffffffu, mnL, o));
            mxP = fmaxf(mxP, __shfl_xor_sync(0xffffffffu, mxP, o));
            mnP = fminf(mnP, __shfl_xor_sync(0xffffffffu, mnP, o));
        }
        if ((t & 31) == 0) {
            int w = t >> 5;
            s_red[0][w] = mxL; s_red[1][w] = mnL; s_red[2][w] = mxP; s_red[3][w] = mnP;
        }
        __syncthreads();
        if (t == 0) {
            float a = s_red[0][0], b = s_red[1][0], c = s_red[2][0], d = s_red[3][0];
            #pragma unroll
            for (int w = 1; w < 16; w++) {
                a = fmaxf(a, s_red[0][w]); b = fminf(b, s_red[1][w]);
                c = fmaxf(c, s_red[2][w]); d = fminf(d, s_red[3][w]);
            }
            atomicMax(&g_rmax[imgL], __float_as_uint(a));
            atomicMin(&g_rmin[imgL], __float_as_uint(b));
            atomicMax(&g_rmax[imgP], __float_as_uint(c));
            atomicMin(&g_rmin[imgP], __float_as_uint(d));
            __threadfence();
            atomicAdd(&g_edone[bat], 1u);
            volatile unsigned* eb = &g_edone[bat];
            while (*eb < 32u) __nanosleep(32);
            __threadfence();
            s_rr[0] = fmaxf(__uint_as_float(*(volatile unsigned*)&g_rmax[imgL]), 1.0f);
            s_rr[1] = fmaxf(__uint_as_float(*(volatile unsigned*)&g_rmin[imgL]), 1.0f);
            s_rr[2] = fmaxf(__uint_as_float(*(volatile unsigned*)&g_rmax[imgP]), 1.0f);
            s_rr[3] = fmaxf(__uint_as_float(*(volatile unsigned*)&g_rmin[imgP]), 1.0f);
        }
        __syncthreads();
    }
    const float rmaxL = s_rr[0], rminL = s_rr[1], rmaxP = s_rr[2], rminP = s_rr[3];
    const float irL = __fdividef(1.0f, rmaxL), irP = __fdividef(1.0f, rmaxP);

    // ---- q-maps + partial sums (pp recomputed from L2-hot ypred) ----
    float t1 = 0.f, d1 = 0.f, t2 = 0.f, d2s = 0.f;
    #pragma unroll
    for (int k = 0; k < 4; k++) {
        int y = ybase + k;
        bool mL = (S.bits[0][y][wc0] >> shbit) & 1u;
        bool mP = (S.bits[1][y][wc0] >> shbit) & 1u;
        bool sL = (S.skelw[0][y] >> skbit) & 1u;
        bool sP = (S.skelw[1][y] >> skbit) & 1u;
        float dl = dm0[k], dp = dm1[k];
        float x  = __ldg(&ypred[bat * 65536 + y * 256 + gc]);
        float p  = __fdividef(1.0f, 1.0f + __expf(-x));
        float pp = __fdividef(1.0f, 1.0f + __expf(1.0f - 2.0f * p));

        float q_vl   = mL ? fminf(dl, rmaxL) * irL : 0.f;
        float q_slvl = sL ? dl * irL : 0.f;
        float q_sl   = sL ? (rmaxL - dl + rminL) * irL : 0.f;
        float q_vp   = mP ? fminf(dp, rmaxP) * irP * pp : 0.f;
        float q_spvp = sP ? dp * irP * pp : 0.f;
        float q_sp   = sP ? (rmaxP - dp + rminP) * irP * pp : 0.f;
        t1  += q_sp * q_vl;
        d1  += (sP && !sL) ? q_spvp * q_sp : q_slvl * q_sp;   // combine_tensors
        t2  += q_sl * q_vp;
        d2s += (sL && !sP) ? q_slvl * q_sl : q_spvp * q_sl;
    }
    #pragma unroll
    for (int o = 16; o; o >>= 1) {
        t1  += __shfl_xor_sync(0xffffffffu, t1,  o);
        d1  += __shfl_xor_sync(0xffffffffu, d1,  o);
        t2  += __shfl_xor_sync(0xffffffffu, t2,  o);
        d2s += __shfl_xor_sync(0xffffffffu, d2s, o);
    }
    if ((t & 31) == 0) {
        int w = t >> 5;
        s_red[0][w] = t1; s_red[1][w] = d1; s_red[2][w] = t2; s_red[3][w] = d2s;
    }
    __syncthreads();
    if (t == 0) {
        double a0 = 0.0, a1 = 0.0, a2 = 0.0, a3 = 0.0;
        #pragma unroll
        for (int w = 0; w < 16; w++) {
            a0 += (double)s_red[0][w]; a1 += (double)s_red[1][w];
            a2 += (double)s_red[2][w]; a3 += (double)s_red[3][w];
        }
        atomicAdd(&g_sums[0], a0);
        atomicAdd(&g_sums[1], a1);
        atomicAdd(&g_sums[2], a2);
        atomicAdd(&g_sums[3], a3);
        __threadfence();
        unsigned done = atomicAdd(&g_count, 1u);
        if (done == NB - 1) {                      // last block: epilogue + reset
            double S1 = atomicAdd(&g_sums[0], 0.0);
            double D1 = atomicAdd(&g_sums[1], 0.0);
            double S2 = atomicAdd(&g_sums[2], 0.0);
            double D2 = atomicAdd(&g_sums[3], 0.0);
            double wp = (S1 + 1.0) / (D1 + 1.0);
            double ws = (S2 + 1.0) / (D2 + 1.0);
            out[0] = (float)(1.0 - 2.0 * (wp * ws) / (wp + ws));
            g_count = 0u;
            #pragma unroll
            for (int i = 0; i < 4; i++) { g_bdone[i] = 0u; g_edone[i] = 0u; g_sums[i] = 0.0; }
            #pragma unroll
            for (int i = 0; i < 8; i++) { g_rmax[i] = 0u; g_rmin[i] = 0x7f7fffffu; }
            __threadfence();
        }
    }
}

// ---------------- launch ----------------
extern "C" void kernel_launch(void* const* d_in, const int* in_sizes, int n_in,
                              void* d_out, int out_size) {
    const float* ypred = (const float*)d_in[0];
    const int*   ytrue = (const int*)d_in[1];
    float*       out   = (float*)d_out;
    k_fused<<<NB, NT>>>(ypred, ytrue, out);
}